// round 16
// baseline (speedup 1.0000x reference)
#include <cuda_runtime.h>
#include <cuda_bf16.h>

// text [SEQ=200, BATCH=4096] int32 (row-major text[s*BATCH+b]),
// w [V=50000] f32, bias [1] f32.  out[b] = sum_{unique t in doc b} w[t] + bias.
//
// R16 = R9/R15 hybrid (proven local optimum: DOCS=4, NTHR=256, grid 1024,
// 6 uniform block syncs, single reused 2048-slot/doc byte table, int4 text
// load, marker-init as latency filler) + ONE delta: the 4 speculative weight
// gathers are SPLIT 2+2 across the first barrier. All resident CTAs (single
// wave, oe~7) were firing their full gather burst into the L1tex FIFO at the
// same instant; per the B300 cross-CTA queue-contention model this burst size
// drives the CTA completion spread. Halving the front burst (consumption is
// in phase 5 — latency budget huge; barriers stop ptxas re-hoisting) targets
// that spread directly.

#define SEQ    200
#define BATCH  4096
#define DOCS   4
#define NTHR   256
#define HBITS  11
#define HSIZE  (1 << HBITS)       // 2048 byte slots per doc, reused across levels

__global__ __launch_bounds__(NTHR, 8)
void MNB_24111946400019_kernel(const int* __restrict__ text,
                               const float* __restrict__ w,
                               const float* __restrict__ bias,
                               float* __restrict__ out)
{
    __shared__ int           toks[DOCS * SEQ];          // 3.2KB, [doc][seq]
    __shared__ unsigned char marker[DOCS * HSIZE];      // 8KB, reused L1/L2/L3
    __shared__ float         part[DOCS][9];

    const int b0  = blockIdx.x * DOCS;
    const int tid = threadIdx.x;
    const bool act = (tid < SEQ);

    int   tt[4];
    float wv[4];
    int   st[4];

    // ── Phase 0: one int4 text load (seq=tid, docs 0..3); HALF the gathers
    //    issue now; marker init is the independent filler. ──
    if (act) {
        const int4 tx = *reinterpret_cast<const int4*>(text + tid * BATCH + b0);
        tt[0] = tx.x; tt[1] = tx.y; tt[2] = tx.z; tt[3] = tx.w;
    } else {
        tt[0] = tt[1] = tt[2] = tt[3] = 0;
    }
    wv[0] = act ? __ldg(&w[tt[0]]) : 0.0f;               // burst half 1
    wv[1] = act ? __ldg(&w[tt[1]]) : 0.0f;
    {
        int4* m4 = reinterpret_cast<int4*>(marker);
        const int4 ff = make_int4(-1, -1, -1, -1);
        m4[tid]        = ff;                             // 8KB filler work
        m4[tid + NTHR] = ff;
    }
    if (act) {
        #pragma unroll
        for (int k = 0; k < 4; ++k) toks[k * SEQ + tid] = tt[k];
    }
    __syncthreads();

    // ── Phase 1: second gather half (de-burst) + level-1 racing byte store ──
    wv[2] = act ? __ldg(&w[tt[2]]) : 0.0f;               // burst half 2
    wv[3] = act ? __ldg(&w[tt[3]]) : 0.0f;
    if (act) {
        #pragma unroll
        for (int k = 0; k < 4; ++k) {
            const unsigned h1 = ((unsigned)tt[k] * 2654435761u) >> (32 - HBITS);
            marker[k * HSIZE + h1] = (unsigned char)tid;
        }
    }
    __syncthreads();

    // ── Phase 2: read level 1 (genuine same-phase racer), classify ──
    #pragma unroll
    for (int k = 0; k < 4; ++k) {
        st[k] = 0;
        if (act) {
            const unsigned h1 = ((unsigned)tt[k] * 2654435761u) >> (32 - HBITS);
            const int m = marker[k * HSIZE + h1];
            if (toks[k * SEQ + m] == tt[k]) st[k] = (m == tid) ? 1 : 0;
            else                            st[k] = 2;          // ~10/doc
        }
    }
    __syncthreads();                     // level-1 reads before level-2 stores

    // ── Phase 3: level-2 store (same table, h2) ──
    #pragma unroll
    for (int k = 0; k < 4; ++k) {
        if (st[k] == 2) {
            const unsigned h2 = ((unsigned)tt[k] * 0x85EBCA77u) >> (32 - HBITS);
            marker[k * HSIZE + h2] = (unsigned char)tid;
        }
    }
    __syncthreads();

    // ── Phase 4: read level 2; leftovers store level 3 (h3) ──
    #pragma unroll
    for (int k = 0; k < 4; ++k) {
        if (st[k] == 2) {
            const unsigned h2 = ((unsigned)tt[k] * 0x85EBCA77u) >> (32 - HBITS);
            const int m = marker[k * HSIZE + h2];
            if (toks[k * SEQ + m] == tt[k]) st[k] = (m == tid) ? 1 : 0;
            else                            st[k] = 3;          // ~0.02/doc
        }
    }
    __syncthreads();
    #pragma unroll
    for (int k = 0; k < 4; ++k) {
        if (st[k] == 3) {
            const unsigned h3 = ((unsigned)tt[k] * 0xC2B2AE3Du) >> (32 - HBITS);
            marker[k * HSIZE + h3] = (unsigned char)tid;
        }
    }
    __syncthreads();

    // ── Phase 5: resolve level 3 / exact scan; accumulate ──
    float v[4];
    #pragma unroll
    for (int k = 0; k < 4; ++k) {
        int c = st[k];
        if (c == 3) {
            const unsigned h3 = ((unsigned)tt[k] * 0xC2B2AE3Du) >> (32 - HBITS);
            const int m = marker[k * HSIZE + h3];
            if (toks[k * SEQ + m] == tt[k]) {
                c = (m == tid) ? 1 : 0;
            } else {
                // Exact first-occurrence scan (~1e-5/doc): exhaustive backstop.
                int f = 0;
                while (toks[k * SEQ + f] != tt[k]) ++f;   // terminates at f==tid
                c = (f == tid) ? 1 : 0;
            }
        }
        v[k] = (c == 1) ? wv[k] : 0.0f;
    }

    // ── Reduction: 4 independent warp reductions, then 32-thread finish ──
    #pragma unroll
    for (int k = 0; k < 4; ++k) {
        float s = v[k];
        s += __shfl_xor_sync(0xffffffffu, s, 16);
        s += __shfl_xor_sync(0xffffffffu, s, 8);
        s += __shfl_xor_sync(0xffffffffu, s, 4);
        s += __shfl_xor_sync(0xffffffffu, s, 2);
        s += __shfl_xor_sync(0xffffffffu, s, 1);
        if ((tid & 31) == 0) part[k][tid >> 5] = s;
    }
    __syncthreads();

    if (tid < 32) {
        const int dd = tid >> 3;                         // doc 0..3
        const int j  = tid & 7;                          // warp slot
        float s = part[dd][j];
        s += __shfl_xor_sync(0xffffffffu, s, 4);
        s += __shfl_xor_sync(0xffffffffu, s, 2);
        s += __shfl_xor_sync(0xffffffffu, s, 1);
        if (j == 0) out[b0 + dd] = s + bias[0];
    }
}

extern "C" void kernel_launch(void* const* d_in, const int* in_sizes, int n_in,
                              void* d_out, int out_size)
{
    const int*   text = (const int*)d_in[0];
    const float* w    = (const float*)d_in[1];
    const float* bias = (const float*)d_in[2];
    float*       out  = (float*)d_out;

    MNB_24111946400019_kernel<<<BATCH / DOCS, NTHR>>>(text, w, bias, out);
}

// round 17
// speedup vs baseline: 1.0208x; 1.0208x over previous
#include <cuda_runtime.h>
#include <cuda_bf16.h>

// text [SEQ=200, BATCH=4096] int32 (row-major text[s*BATCH+b]),
// w [V=50000] f32, bias [1] f32.  out[b] = sum_{unique t in doc b} w[t] + bias.
//
// R17 = R9 VERBATIM (best measured: kernel 8.54us, total 10.72us; every
// structural deviation in R10-R16 regressed or was flat) + one strictly
// work-reducing micro-fix: speculative gathers are predicated on item
// validity, removing the 224 dummy w[0] gather lanes per block (~22% of the
// gather stream) that R9 issued unconditionally. No structural change.

#define SEQ    200
#define BATCH  4096
#define DOCS   4
#define NTHR   256
#define NITEM  (SEQ * DOCS)       // 800
#define HBITS  11
#define HSIZE  (1 << HBITS)       // 2048 slots per doc

__global__ __launch_bounds__(NTHR, 8)
void MNB_24111946400019_kernel(const int* __restrict__ text,
                               const float* __restrict__ w,
                               const float* __restrict__ bias,
                               float* __restrict__ out)
{
    __shared__ int           toks[DOCS * SEQ];          // 3.2KB
    __shared__ unsigned char marker[DOCS * HSIZE];      // 8KB
    __shared__ float         part[DOCS][9];

    const int b0  = blockIdx.x * DOCS;
    const int tid = threadIdx.x;
    const int d   = tid & 3;                 // this thread's doc (256%4==0)
    const int dt  = d * SEQ;
    const int dm  = d * HSIZE;

    // Text load (item i=s*4+d: 4 lanes per 16B sector) + speculative gathers
    // (predicated: only real items) issued immediately so L2 latency hides
    // under the dedup sequence. Marker init is the independent filler.
    int   tt[4];
    float wv[4];
    #pragma unroll
    for (int k = 0; k < 4; ++k) {
        const int i = tid + k * NTHR;
        const int s = i >> 2;
        tt[k] = (i < NITEM) ? __ldg(&text[s * BATCH + b0 + d]) : 0;
    }
    #pragma unroll
    for (int k = 0; k < 4; ++k)
        wv[k] = (tid + k * NTHR < NITEM) ? __ldg(&w[tt[k]]) : 0.0f;   // in flight

    // Init markers to 0xFF (seq idx 0..199 < 255): 512 int4 stores.
    {
        int4* m4 = reinterpret_cast<int4*>(marker);
        const int4 ff = make_int4(-1, -1, -1, -1);
        m4[tid]        = ff;
        m4[tid + NTHR] = ff;
    }
    #pragma unroll
    for (int k = 0; k < 4; ++k) {
        const int i = tid + k * NTHR;
        if (i < NITEM) toks[dt + (i >> 2)] = tt[k];
    }
    __syncthreads();

    int st[4];                               // 0=drop, 1=contribute, 2/3=unresolved
    unsigned hh[4];

    // ── Level 1 race ──
    #pragma unroll
    for (int k = 0; k < 4; ++k) {
        const int i = tid + k * NTHR;
        hh[k] = ((unsigned)tt[k] * 2654435761u) >> (32 - HBITS);
        if (i < NITEM) marker[dm + hh[k]] = (unsigned char)(i >> 2);
    }
    __syncthreads();
    #pragma unroll
    for (int k = 0; k < 4; ++k) {
        st[k] = 0;
        const int i = tid + k * NTHR;
        if (i < NITEM) {
            const int m = marker[dm + hh[k]];      // genuine same-phase racer
            if (toks[dt + m] == tt[k]) st[k] = (m == (i >> 2)) ? 1 : 0;
            else                       st[k] = 2;  // ~9.8/doc
        }
    }
    __syncthreads();

    // ── Level 2 race (h2) ──
    #pragma unroll
    for (int k = 0; k < 4; ++k) {
        hh[k] = ((unsigned)tt[k] * 0x85EBCA77u) >> (32 - HBITS);
        if (st[k] == 2) marker[dm + hh[k]] = (unsigned char)((tid + k * NTHR) >> 2);
    }
    __syncthreads();
    #pragma unroll
    for (int k = 0; k < 4; ++k) {
        if (st[k] == 2) {
            const int m = marker[dm + hh[k]];
            if (toks[dt + m] == tt[k]) st[k] = (m == ((tid + k * NTHR) >> 2)) ? 1 : 0;
            else                       st[k] = 3;  // ~0.02/doc
        }
    }
    __syncthreads();

    // ── Level 3 race (h3) ──
    #pragma unroll
    for (int k = 0; k < 4; ++k) {
        hh[k] = ((unsigned)tt[k] * 0xC2B2AE3Du) >> (32 - HBITS);
        if (st[k] == 3) marker[dm + hh[k]] = (unsigned char)((tid + k * NTHR) >> 2);
    }
    __syncthreads();

    float v = 0.0f;
    #pragma unroll
    for (int k = 0; k < 4; ++k) {
        const int s = (tid + k * NTHR) >> 2;
        int c = st[k];
        if (c == 3) {
            const int m = marker[dm + hh[k]];
            if (toks[dt + m] == tt[k]) {
                c = (m == s) ? 1 : 0;
            } else {
                // Level 4 (~1e-5/doc): exact first-occurrence scan.
                int f = 0;
                while (toks[dt + f] != tt[k]) ++f;
                c = (f == s) ? 1 : 0;
            }
        }
        if (c == 1) v += wv[k];
    }

    // ── Per-doc reduction: lanes with equal (lane&3) share a doc ──
    v += __shfl_xor_sync(0xffffffffu, v, 16);
    v += __shfl_xor_sync(0xffffffffu, v, 8);
    v += __shfl_xor_sync(0xffffffffu, v, 4);
    if ((tid & 31) < 4) part[d][tid >> 5] = v;           // 8 warps
    __syncthreads();

    if (tid < 32) {
        const int dd = tid >> 3;                         // doc 0..3
        const int j  = tid & 7;                          // warp slot
        float s = part[dd][j];
        s += __shfl_xor_sync(0xffffffffu, s, 4);
        s += __shfl_xor_sync(0xffffffffu, s, 2);
        s += __shfl_xor_sync(0xffffffffu, s, 1);
        if (j == 0) out[b0 + dd] = s + bias[0];
    }
}

extern "C" void kernel_launch(void* const* d_in, const int* in_sizes, int n_in,
                              void* d_out, int out_size)
{
    const int*   text = (const int*)d_in[0];
    const float* w    = (const float*)d_in[1];
    const float* bias = (const float*)d_in[2];
    float*       out  = (float*)d_out;

    MNB_24111946400019_kernel<<<BATCH / DOCS, NTHR>>>(text, w, bias, out);
}